// round 4
// baseline (speedup 1.0000x reference)
#include <cuda_runtime.h>

// Problem constants (fixed shapes)
#define DIM     64
#define NS      16          // neighbors S
#define PP      16          // points per block
#define NTHREADS 256
#define NPTS    16384
#define NB      4
#define QSCALE  0.125f      // 64^-0.5

// shared carve (floats):
// wks 4096 (row-major) | wvT 4096 (transposed) | wps 256 | bps 64 |
// ncs 64*257 | nxs 768 | xs 48 | qks 16*65 | qps 64 | qbs 16 | qac 1040
#define SM_FLOATS (4096 + 4096 + 256 + 64 + 64*257 + 768 + 48 + 1040 + 64 + 16 + 1040)
#define SM_BYTES  (SM_FLOATS * 4)

extern __shared__ float sm[];

__global__ void __launch_bounds__(NTHREADS, 2)
pt_attn_kernel(const float* __restrict__ xyz,        // [B,3,N]
               const float* __restrict__ nxyz,       // [B,3,N,S]
               const float* __restrict__ point,      // [B,C,N]
               const float* __restrict__ ncost,      // [B,C,N,S]
               const float* __restrict__ w_k,        // [64,64] row-major [o,c]
               const float* __restrict__ w_v,        // [64,64]
               const float* __restrict__ w_pos,      // [64,4]  ([c_in, d])
               const float* __restrict__ b_pos,      // [64]
               float* __restrict__ out)              // [B,C,N]
{
    float* wks = sm;                    // [o*64+c]  (row-major, for W_k^T q)
    float* wvT = wks + 4096;            // [c*64+o]  (transposed, for W_v acc)
    float* wps = wvT + 4096;            // [c*4+d]
    float* bps = wps + 256;             // [c]
    float* ncs = bps + 64;              // [c*257 + p*16 + s]
    float* nxs = ncs + 64*257;          // [d*256 + p*16 + s]
    float* xs  = nxs + 768;             // [d*16 + p]
    float* qks = xs + 48;               // [p*65 + c]   qk = W_k^T q
    float* qps = qks + PP*65;           // [p*4 + d]
    float* qbs = qps + 64;              // [p]
    float* qac = qbs + 16;              // phase1: q [o*16+p]; phase3+: acc [p*65+c]

    const int tid = threadIdx.x;
    const int blk = blockIdx.x;
    const int b   = blk >> 10;              // N/PP = 1024 tiles per batch
    const int n0  = (blk & 1023) * PP;

    // ------------------------- load phase -------------------------
    for (int i = tid; i < 4096; i += NTHREADS) {
        wks[i] = w_k[i];                                  // keep [o][c]
        wvT[(i & 63) * 64 + (i >> 6)] = w_v[i];           // transpose to [c][o]
    }
    if (tid < 256) wps[tid] = w_pos[tid];
    if (tid < 64)  bps[tid] = b_pos[tid];
    if (tid < 48) {
        int d = tid >> 4, p = tid & 15;
        xs[tid] = xyz[(size_t)(b * 3 + d) * NPTS + n0 + p];
    }
    for (int i = tid; i < 768; i += NTHREADS) {
        int d = i >> 8, j = i & 255;
        nxs[i] = nxyz[((size_t)(b * 3 + d) * NPTS + n0) * NS + j];
    }
    for (int i = tid; i < 1024; i += NTHREADS) {
        int c = i >> 4, p = i & 15;
        qac[c * 16 + p] = point[(size_t)(b * DIM + c) * NPTS + n0 + p] * QSCALE;
    }
    {
        const float4* src = reinterpret_cast<const float4*>(ncost);
        for (int i = tid; i < 4096; i += NTHREADS) {
            int c = i >> 6, f = i & 63;   // 64 float4 per channel row (256 floats)
            size_t base4 = ((size_t)(b * DIM + c) * NPTS + n0) * 4;  // *NS/4
            float4 v = src[base4 + f];
            float* dst = ncs + c * 257 + f * 4;
            dst[0] = v.x; dst[1] = v.y; dst[2] = v.z; dst[3] = v.w;
        }
    }
    __syncthreads();

    // ------------------------- qk = W_k^T q  (qk[c] = sum_o W_k[o][c] q[o]) ----
    {
        const int c = tid & 63, pb = tid >> 6;   // pb in 0..3
        float a0 = 0.f, a1 = 0.f, a2 = 0.f, a3 = 0.f;
        #pragma unroll 8
        for (int o = 0; o < 64; o++) {
            float w = wks[o * 64 + c];
            a0 += w * qac[o * 16 + pb];
            a1 += w * qac[o * 16 + pb + 4];
            a2 += w * qac[o * 16 + pb + 8];
            a3 += w * qac[o * 16 + pb + 12];
        }
        qks[(pb     ) * 65 + c] = a0;
        qks[(pb +  4) * 65 + c] = a1;
        qks[(pb +  8) * 65 + c] = a2;
        qks[(pb + 12) * 65 + c] = a3;
    }
    __syncthreads();

    // ------------------------- qp = W_pos^T qk,  qb = qk . b_pos -------------------------
    if (tid < 80) {
        int p = tid / 5, r = tid % 5;
        float a = 0.f;
        if (r < 4) {
            #pragma unroll 8
            for (int c = 0; c < 64; c++) a += wps[c * 4 + r] * qks[p * 65 + c];
            qps[p * 4 + r] = a;
        } else {
            #pragma unroll 8
            for (int c = 0; c < 64; c++) a += bps[c] * qks[p * 65 + c];
            qbs[p] = a;
        }
    }
    __syncthreads();

    // ------------------------- attention logits + softmax + weighted nc sum -------------------------
    const int p = tid >> 4, s = tid & 15;   // 16 lanes per point, 2 points per warp
    {
        float dx = xs[p]      - nxs[        p * 16 + s];
        float dy = xs[16 + p] - nxs[256 + p * 16 + s];
        float dz = xs[32 + p] - nxs[512 + p * 16 + s];
        float nrm = sqrtf(dx * dx + dy * dy + dz * dz);
        float a = qbs[p] + qps[p * 4 + 0] * dx + qps[p * 4 + 1] * dy
                         + qps[p * 4 + 2] * dz + qps[p * 4 + 3] * nrm;
        const float* qkp = qks + p * 65;
        const float* ncp = ncs + p * 16 + s;
        #pragma unroll 8
        for (int c = 0; c < 64; c++) a += qkp[c] * ncp[c * 257];

        // softmax across the 16 lanes of this point
        float m = a;
        #pragma unroll
        for (int off = 8; off; off >>= 1)
            m = fmaxf(m, __shfl_xor_sync(0xffffffffu, m, off, 16));
        float e = __expf(a - m);
        float den = e;
        #pragma unroll
        for (int off = 8; off; off >>= 1)
            den += __shfl_xor_sync(0xffffffffu, den, off, 16);
        float w = e / den;

        // acc[c] = sum_s w_s * nc[c][s]; lane index reused as channel group
        float ac0 = 0.f, ac1 = 0.f, ac2 = 0.f, ac3 = 0.f;
        const int t16 = s;
        #pragma unroll
        for (int s2 = 0; s2 < 16; s2++) {
            float ws = __shfl_sync(0xffffffffu, w, s2, 16);
            const float* row = ncs + p * 16 + s2;
            ac0 += ws * row[(t16     ) * 257];
            ac1 += ws * row[(t16 + 16) * 257];
            ac2 += ws * row[(t16 + 32) * 257];
            ac3 += ws * row[(t16 + 48) * 257];
        }
        // stash acc into qac (q is dead; sync separates the uses)
        qac[p * 65 + t16     ] = ac0;
        qac[p * 65 + t16 + 16] = ac1;
        qac[p * 65 + t16 + 32] = ac2;
        qac[p * 65 + t16 + 48] = ac3;
    }
    __syncthreads();

    // ------------------------- out = W_v . acc -------------------------
    {
        const int po = tid & 15;
        const int ob = (tid >> 4) * 4;
        float r0 = 0.f, r1 = 0.f, r2 = 0.f, r3 = 0.f;
        const float* accp = qac + po * 65;
        #pragma unroll 8
        for (int c = 0; c < 64; c++) {
            float av = accp[c];
            float4 wv4 = *reinterpret_cast<const float4*>(wvT + c * 64 + ob);
            r0 += av * wv4.x; r1 += av * wv4.y; r2 += av * wv4.z; r3 += av * wv4.w;
        }
        size_t ob_base = (size_t)(b * DIM + ob) * NPTS + n0 + po;
        out[ob_base             ] = r0;
        out[ob_base + 1ull*NPTS ] = r1;
        out[ob_base + 2ull*NPTS ] = r2;
        out[ob_base + 3ull*NPTS ] = r3;
    }
}

extern "C" void kernel_launch(void* const* d_in, const int* in_sizes, int n_in,
                              void* d_out, int out_size) {
    (void)in_sizes; (void)n_in; (void)out_size;
    const float* xyz    = (const float*)d_in[0];
    const float* nxyz   = (const float*)d_in[1];
    const float* point  = (const float*)d_in[2];
    // d_in[3] = neighbor_points: unused by the reference math
    const float* ncost  = (const float*)d_in[4];
    const float* w_k    = (const float*)d_in[5];
    const float* w_v    = (const float*)d_in[6];
    const float* w_pos  = (const float*)d_in[7];
    const float* b_pos  = (const float*)d_in[8];
    float* out = (float*)d_out;

    cudaFuncSetAttribute(pt_attn_kernel,
                         cudaFuncAttributeMaxDynamicSharedMemorySize, SM_BYTES);

    dim3 grid(NB * (NPTS / PP));   // 4096 blocks
    pt_attn_kernel<<<grid, NTHREADS, SM_BYTES>>>(
        xyz, nxyz, point, ncost, w_k, w_v, w_pos, b_pos, out);
}

// round 8
// speedup vs baseline: 1.4459x; 1.4459x over previous
#include <cuda_runtime.h>

// Problem constants (fixed shapes)
#define DIM     64
#define NS      16          // neighbors S
#define PP      16          // points per tile
#define TPB     4           // tiles per block
#define NTHREADS 256
#define NPTS    16384
#define NB      4
#define QSCALE  0.125f      // 64^-0.5

// shared carve (floats), all weight-like arrays padded to stride 65:
// wks 64*65 | wvT 64*65 | wps 256 | bps 64 | ncs 64*257 | nxs 768 | xs 48 |
// qks 16*65 | qps 64 | qbs 16 | qac 1040
#define SM_FLOATS (4160 + 4160 + 256 + 64 + 64*257 + 768 + 48 + 1040 + 64 + 16 + 1040)
#define SM_BYTES  (SM_FLOATS * 4)

extern __shared__ float sm[];

__global__ void __launch_bounds__(NTHREADS, 2)
pt_attn_kernel(const float* __restrict__ xyz,        // [B,3,N]
               const float* __restrict__ nxyz,       // [B,3,N,S]
               const float* __restrict__ point,      // [B,C,N]
               const float* __restrict__ ncost,      // [B,C,N,S]
               const float* __restrict__ w_k,        // [64,64] row-major [o,c]
               const float* __restrict__ w_v,        // [64,64]
               const float* __restrict__ w_pos,      // [64,4]  ([o,d])
               const float* __restrict__ b_pos,      // [64]
               float* __restrict__ out)              // [B,C,N]
{
    float* wks = sm;                    // [o*65 + c]  row-major padded
    float* wvT = wks + 4160;            // [c*65 + o]  transposed padded
    float* wps = wvT + 4160;            // [o*4 + d]
    float* bps = wps + 256;             // [o]
    float* ncs = bps + 64;              // [c*257 + p*16 + s]
    float* nxs = ncs + 64*257;          // [d*256 + p*16 + s]
    float* xs  = nxs + 768;             // [d*16 + p]
    float* qks = xs + 48;               // [p*65 + c]   qk = W_k^T q
    float* qps = qks + PP*65;           // [p*4 + d]
    float* qbs = qps + 64;              // [p]
    float* qac = qbs + 16;              // phase1: q [o*16+p]; later: acc [p*65+c]

    const int tid = threadIdx.x;
    const int blk = blockIdx.x;
    const int b   = blk >> 8;                 // 256 blocks per batch
    const int t0  = (blk & 255) * TPB;        // first tile index within batch

    // ------------------- weights: load once per block -------------------
    for (int i = tid; i < 4096; i += NTHREADS) {
        int r = i >> 6, c = i & 63;
        wks[r * 65 + c] = w_k[i];             // row-major padded: conflict-free
        wvT[c * 65 + r] = w_v[i];             // transposed padded: banks (c+r)%32 distinct
    }
    if (tid < 256) wps[tid] = w_pos[tid];
    if (tid < 64)  bps[tid] = b_pos[tid];

    for (int t = 0; t < TPB; t++) {
        const int n0 = (t0 + t) * PP;

        // ------------------- per-tile loads -------------------
        if (tid < 48) {
            int d = tid >> 4, p = tid & 15;
            xs[tid] = xyz[(size_t)(b * 3 + d) * NPTS + n0 + p];
        }
        for (int i = tid; i < 768; i += NTHREADS) {
            int d = i >> 8, j = i & 255;
            nxs[i] = nxyz[((size_t)(b * 3 + d) * NPTS + n0) * NS + j];
        }
        for (int i = tid; i < 1024; i += NTHREADS) {
            int c = i >> 4, p = i & 15;
            qac[c * 16 + p] = point[(size_t)(b * DIM + c) * NPTS + n0 + p] * QSCALE;
        }
        {
            const float4* src = reinterpret_cast<const float4*>(ncost);
            for (int i = tid; i < 4096; i += NTHREADS) {
                int c = i >> 6, f = i & 63;   // 64 float4 per channel row
                size_t base4 = ((size_t)(b * DIM + c) * NPTS + n0) * 4;
                float4 v = src[base4 + f];
                float* dst = ncs + c * 257 + f * 4;
                dst[0] = v.x; dst[1] = v.y; dst[2] = v.z; dst[3] = v.w;
            }
        }
        __syncthreads();

        // ------------------- qk = W_k^T q  (qk[c] = sum_o W_k[o][c] q[o]) ----
        {
            const int c = tid & 63, pb = tid >> 6;   // pb in 0..3
            float a0 = 0.f, a1 = 0.f, a2 = 0.f, a3 = 0.f;
            #pragma unroll 8
            for (int o = 0; o < 64; o++) {
                float w = wks[o * 65 + c];
                a0 += w * qac[o * 16 + pb];
                a1 += w * qac[o * 16 + pb + 4];
                a2 += w * qac[o * 16 + pb + 8];
                a3 += w * qac[o * 16 + pb + 12];
            }
            qks[(pb     ) * 65 + c] = a0;
            qks[(pb +  4) * 65 + c] = a1;
            qks[(pb +  8) * 65 + c] = a2;
            qks[(pb + 12) * 65 + c] = a3;
        }
        __syncthreads();

        // ------------------- qp = W_pos^T qk,  qb = qk . b_pos -------------
        if (tid < 80) {
            int p = tid / 5, r = tid % 5;
            float a = 0.f;
            if (r < 4) {
                #pragma unroll 8
                for (int o = 0; o < 64; o++) a += wps[o * 4 + r] * qks[p * 65 + o];
                qps[p * 4 + r] = a;
            } else {
                #pragma unroll 8
                for (int o = 0; o < 64; o++) a += bps[o] * qks[p * 65 + o];
                qbs[p] = a;
            }
        }
        __syncthreads();

        // ------------- logits + softmax + weighted nc sum -------------
        const int p = tid >> 4, s = tid & 15;   // 16 lanes per point
        {
            float dx = xs[p]      - nxs[        p * 16 + s];
            float dy = xs[16 + p] - nxs[256 + p * 16 + s];
            float dz = xs[32 + p] - nxs[512 + p * 16 + s];
            float nrm = sqrtf(dx * dx + dy * dy + dz * dz);
            float a = qbs[p] + qps[p * 4 + 0] * dx + qps[p * 4 + 1] * dy
                             + qps[p * 4 + 2] * dz + qps[p * 4 + 3] * nrm;
            const float* qkp = qks + p * 65;
            const float* ncp = ncs + p * 16 + s;
            #pragma unroll 8
            for (int c = 0; c < 64; c++) a += qkp[c] * ncp[c * 257];

            // softmax across the 16 lanes of this point
            float m = a;
            #pragma unroll
            for (int off = 8; off; off >>= 1)
                m = fmaxf(m, __shfl_xor_sync(0xffffffffu, m, off, 16));
            float e = __expf(a - m);
            float den = e;
            #pragma unroll
            for (int off = 8; off; off >>= 1)
                den += __shfl_xor_sync(0xffffffffu, den, off, 16);
            float w = e / den;

            // acc[c] = sum_s w_s * nc[c][s]; lane index reused as channel group
            float ac0 = 0.f, ac1 = 0.f, ac2 = 0.f, ac3 = 0.f;
            const int t16 = s;
            #pragma unroll
            for (int s2 = 0; s2 < 16; s2++) {
                float ws = __shfl_sync(0xffffffffu, w, s2, 16);
                const float* row = ncs + p * 16 + s2;
                ac0 += ws * row[(t16     ) * 257];
                ac1 += ws * row[(t16 + 16) * 257];
                ac2 += ws * row[(t16 + 32) * 257];
                ac3 += ws * row[(t16 + 48) * 257];
            }
            __syncthreads();   // q staging in qac fully dead; now reuse as acc
            qac[p * 65 + t16     ] = ac0;
            qac[p * 65 + t16 + 16] = ac1;
            qac[p * 65 + t16 + 32] = ac2;
            qac[p * 65 + t16 + 48] = ac3;
        }
        __syncthreads();

        // ------------------- out = W_v . acc -------------------
        {
            const int po = tid & 15;
            const int ob = (tid >> 4) * 4;
            float r0 = 0.f, r1 = 0.f, r2 = 0.f, r3 = 0.f;
            const float* accp = qac + po * 65;
            #pragma unroll 8
            for (int c = 0; c < 64; c++) {
                float av = accp[c];
                const float* wv = wvT + c * 65 + ob;
                r0 += av * wv[0]; r1 += av * wv[1];
                r2 += av * wv[2]; r3 += av * wv[3];
            }
            size_t ob_base = (size_t)(b * DIM + ob) * NPTS + n0 + po;
            out[ob_base             ] = r0;
            out[ob_base + 1ull*NPTS ] = r1;
            out[ob_base + 2ull*NPTS ] = r2;
            out[ob_base + 3ull*NPTS ] = r3;
        }
        __syncthreads();   // protect qac/ncs/nxs/xs before next tile's loads
    }
}

extern "C" void kernel_launch(void* const* d_in, const int* in_sizes, int n_in,
                              void* d_out, int out_size) {
    (void)in_sizes; (void)n_in; (void)out_size;
    const float* xyz    = (const float*)d_in[0];
    const float* nxyz   = (const float*)d_in[1];
    const float* point  = (const float*)d_in[2];
    // d_in[3] = neighbor_points: unused by the reference math
    const float* ncost  = (const float*)d_in[4];
    const float* w_k    = (const float*)d_in[5];
    const float* w_v    = (const float*)d_in[6];
    const float* w_pos  = (const float*)d_in[7];
    const float* b_pos  = (const float*)d_in[8];
    float* out = (float*)d_out;

    cudaFuncSetAttribute(pt_attn_kernel,
                         cudaFuncAttributeMaxDynamicSharedMemorySize, SM_BYTES);

    dim3 grid(NB * (NPTS / PP) / TPB);   // 1024 blocks, 4 tiles each
    pt_attn_kernel<<<grid, NTHREADS, SM_BYTES>>>(
        xyz, nxyz, point, ncost, w_k, w_v, w_pos, b_pos, out);
}